// round 3
// baseline (speedup 1.0000x reference)
#include <cuda_runtime.h>
#include <cstdint>
#include <cstddef>

#define A_DIM 64
#define B_DIM 256
#define D_DIM 128
#define H_DIM 512
#define G4    2048
#define NCTA  128
#define TPB   256
#define NCOLS 256

// ---------------- device scratch (static: no allocations allowed) ----------------
__device__ float g_pre_enc[A_DIM * G4];                       // 512 KB
__device__ float g_pre_dec[(size_t)NCOLS * A_DIM * G4];       // 134 MB
__device__ float g_h[2][H_DIM];                               // double-buffered hidden state
__device__ float g_outs[NCOLS * D_DIM];                       // per-column projections
__device__ __align__(128) unsigned int g_flags[NCTA];         // per-CTA arrival flags

// ---------------- pre-activation GEMM: pre[m][g] = bih[g]+bhh[g] + dot(Wih[g,:], x_row(m)) ----
#define BM 64
#define BN 64
#define BK 64

__global__ void pre_gemm_kernel(const float* __restrict__ x,
                                const float* __restrict__ Wih,
                                const float* __restrict__ bih,
                                const float* __restrict__ bhh,
                                int dec)
{
    __shared__ float Xs[BM][BK + 1];
    __shared__ float Ws[BN][BK + 1];
    float* __restrict__ outp = dec ? g_pre_dec : g_pre_enc;

    const int m0 = blockIdx.x * BM;
    const int n0 = blockIdx.y * BN;
    const int tid = threadIdx.x;
    const int tx = tid & 15;
    const int ty = tid >> 4;

    float acc[4][4];
#pragma unroll
    for (int r = 0; r < 4; r++)
#pragma unroll
        for (int c = 0; c < 4; c++) acc[r][c] = 0.f;

    const int lr = tid >> 2;         // 0..63 (row this thread loads)
    const int lc = (tid & 3) * 16;   // 0,16,32,48

#pragma unroll
    for (int kit = 0; kit < 2; kit++) {
        const int k0 = kit * BK;
        // X tile (gathered rows)
        {
            const int m = m0 + lr;
            const float* src;
            if (dec) {
                const int i = m >> 6;       // column index
                const int t = m & 63;       // timestep
                src = x + ((size_t)(t * B_DIM + (B_DIM - 1 - i))) * D_DIM + k0 + lc;
            } else {
                src = x + ((size_t)(m * B_DIM + (B_DIM - 1))) * D_DIM + k0 + lc;
            }
#pragma unroll
            for (int q = 0; q < 4; q++) {
                float4 v = *(const float4*)(src + q * 4);
                Xs[lr][lc + q * 4 + 0] = v.x;
                Xs[lr][lc + q * 4 + 1] = v.y;
                Xs[lr][lc + q * 4 + 2] = v.z;
                Xs[lr][lc + q * 4 + 3] = v.w;
            }
        }
        // W tile
        {
            const int g = n0 + lr;
            const float* src = Wih + (size_t)g * D_DIM + k0 + lc;
#pragma unroll
            for (int q = 0; q < 4; q++) {
                float4 v = *(const float4*)(src + q * 4);
                Ws[lr][lc + q * 4 + 0] = v.x;
                Ws[lr][lc + q * 4 + 1] = v.y;
                Ws[lr][lc + q * 4 + 2] = v.z;
                Ws[lr][lc + q * 4 + 3] = v.w;
            }
        }
        __syncthreads();
#pragma unroll 16
        for (int kk = 0; kk < BK; kk++) {
            float a[4], bb[4];
#pragma unroll
            for (int r = 0; r < 4; r++) a[r] = Xs[ty * 4 + r][kk];
#pragma unroll
            for (int c = 0; c < 4; c++) bb[c] = Ws[tx * 4 + c][kk];
#pragma unroll
            for (int r = 0; r < 4; r++)
#pragma unroll
                for (int c = 0; c < 4; c++) acc[r][c] = fmaf(a[r], bb[c], acc[r][c]);
        }
        __syncthreads();
    }
#pragma unroll
    for (int r = 0; r < 4; r++) {
        const int m = m0 + ty * 4 + r;
#pragma unroll
        for (int c = 0; c < 4; c++) {
            const int g = n0 + tx * 4 + c;
            outp[(size_t)m * G4 + g] = acc[r][c] + bih[g] + bhh[g];
        }
    }
}

// ---------------- init (runs every launch: reset flags + h0) ----------------
__global__ void init_kernel()
{
    const int t = threadIdx.x;
    if (t < H_DIM) { g_h[0][t] = 0.f; g_h[1][t] = 0.f; }
    if (t < NCTA) g_flags[t] = 0u;
}

// ---------------- fast activations (MUFU tanh) ----------------
__device__ __forceinline__ float tanh_fast(float x)
{
    float y;
    asm("tanh.approx.f32 %0, %1;" : "=f"(y) : "f"(x));
    return y;
}
__device__ __forceinline__ float sigm(float x)
{
    return fmaf(tanh_fast(0.5f * x), 0.5f, 0.5f);
}

// ---------------- sequential recurrent kernel ----------------
__global__ void __launch_bounds__(TPB, 1) lstm_seq_kernel(
    const float* __restrict__ enc_Whh,
    const float* __restrict__ dec_Whh,
    const float* __restrict__ lin_W,
    const float* __restrict__ lin_b)
{
    __shared__ float s_g[16];    // gates [type*4 + jloc]
    __shared__ float s_c[4];     // cell state owned by this CTA
    __shared__ float s_red[8];   // projection partials

    const int b    = blockIdx.x;
    const int tid  = threadIdx.x;
    const int w    = tid >> 5;
    const int lane = tid & 31;
    const int lg   = 2 * w + (lane >> 4);   // local gate 0..15  (= type*4 + jloc)
    const int p    = lane & 15;             // k-partition 0..15
    const int jloc = lg & 3;
    const int type = lg >> 2;
    const int grow = type * H_DIM + b * 4 + jloc;  // global gate row
    const int k0   = p * 32;

    // persistent recurrent weights in registers (4 MB total across grid)
    float we[32], wd[32];
#pragma unroll
    for (int m = 0; m < 32; m++) we[m] = enc_Whh[(size_t)grow * H_DIM + k0 + m];
#pragma unroll
    for (int m = 0; m < 32; m++) wd[m] = dec_Whh[(size_t)grow * H_DIM + k0 + m];
    const float lw0 = lin_W[b * H_DIM + 2 * tid];
    const float lw1 = lin_W[b * H_DIM + 2 * tid + 1];
    const float lb  = lin_b[b];

    if (tid < 4) s_c[tid] = 0.f;
    unsigned bar = 0;
    int buf = 0;
    __syncthreads();

    auto step = [&](const float (&wr)[32], const float* __restrict__ pre) {
        const float prev = __ldg(pre + grow);
        const float4* hp = (const float4*)(&g_h[buf][k0]);
        float4 hv[8];
#pragma unroll
        for (int q = 0; q < 8; q++) hv[q] = __ldcg(hp + q);   // L2 (bypass stale L1)
        float s0 = 0.f, s1 = 0.f, s2 = 0.f, s3 = 0.f;
#pragma unroll
        for (int q = 0; q < 8; q++) {
            s0 = fmaf(wr[4 * q + 0], hv[q].x, s0);
            s1 = fmaf(wr[4 * q + 1], hv[q].y, s1);
            s2 = fmaf(wr[4 * q + 2], hv[q].z, s2);
            s3 = fmaf(wr[4 * q + 3], hv[q].w, s3);
        }
        float sum = (s0 + s1) + (s2 + s3);
        sum += __shfl_xor_sync(0xffffffffu, sum, 1);
        sum += __shfl_xor_sync(0xffffffffu, sum, 2);
        sum += __shfl_xor_sync(0xffffffffu, sum, 4);
        sum += __shfl_xor_sync(0xffffffffu, sum, 8);
        if (p == 0) s_g[lg] = sum + prev;
        __syncthreads();
        if (tid < 4) {
            const float gi = s_g[tid];
            const float gf = s_g[4 + tid];
            const float gg = s_g[8 + tid];
            const float go = s_g[12 + tid];
            const float c  = s_c[tid];
            const float cn = fmaf(sigm(gf), c, sigm(gi) * tanh_fast(gg));
            const float hn = sigm(go) * tanh_fast(cn);
            s_c[tid] = cn;
            g_h[buf ^ 1][b * 4 + tid] = hn;
        }
        __syncthreads();             // orders the h stores before the release below
        bar++;
        if (tid == 0) {
            // one private flag per CTA: parallel, contention-free arrival
            asm volatile("st.release.gpu.global.u32 [%0], %1;"
                         :: "l"(g_flags + b), "r"(bar) : "memory");
        }
        // distributed wait: 128 lanes each poll one CTA's flag
        if (w < 4) {
            const unsigned* fp = g_flags + (w * 32 + lane);
            unsigned v;
            do {
                asm volatile("ld.acquire.gpu.global.u32 %0, [%1];"
                             : "=r"(v) : "l"(fp) : "memory");
            } while (__any_sync(0xffffffffu, v < bar));
        }
        __syncthreads();             // propagate acquire to all warps
        buf ^= 1;
    };

    auto proj = [&](int i) {
        // out_{i}[d=b] = lin_b[b] + dot(lin_W[b,:], h)   (uses h BEFORE column i's steps)
        const float hv0 = __ldcg(&g_h[buf][2 * tid]);
        const float hv1 = __ldcg(&g_h[buf][2 * tid + 1]);
        float v = fmaf(lw0, hv0, lw1 * hv1);
#pragma unroll
        for (int m = 16; m >= 1; m >>= 1) v += __shfl_xor_sync(0xffffffffu, v, m);
        if (lane == 0) s_red[w] = v;
        __syncthreads();
        if (tid == 0) {
            float s = lb;
#pragma unroll
            for (int q = 0; q < 8; q++) s += s_red[q];
            g_outs[(NCOLS - 1 - i) * D_DIM + b] = s;
        }
        __syncthreads();
    };

    // ---- encoder: 64 steps on batch row 255 only ----
    for (int t = 0; t < A_DIM; t++) step(we, g_pre_enc + (size_t)t * G4);

    // ---- decoder: 256 columns; projection first, then 64 steps (last column's steps are dead) ----
    for (int i = 0; i < NCOLS; i++) {
        proj(i);
        if (i < NCOLS - 1) {
            const float* pbase = g_pre_dec + (size_t)i * A_DIM * G4;
            for (int t = 0; t < A_DIM; t++) step(wd, pbase + (size_t)t * G4);
        }
    }
}

// ---------------- broadcast outs (256x128) over leading A dim -> (64,256,128) ----------------
__global__ void bcast_kernel(float* __restrict__ out)
{
    const unsigned idx = blockIdx.x * blockDim.x + threadIdx.x;
    out[idx] = g_outs[idx & (NCOLS * D_DIM - 1)];
}

// ---------------- launch ----------------
extern "C" void kernel_launch(void* const* d_in, const int* in_sizes, int n_in,
                              void* d_out, int out_size)
{
    const float* x       = (const float*)d_in[0];
    const float* enc_Wih = (const float*)d_in[1];
    const float* enc_Whh = (const float*)d_in[2];
    const float* enc_bih = (const float*)d_in[3];
    const float* enc_bhh = (const float*)d_in[4];
    const float* dec_Wih = (const float*)d_in[5];
    const float* dec_Whh = (const float*)d_in[6];
    const float* dec_bih = (const float*)d_in[7];
    const float* dec_bhh = (const float*)d_in[8];
    const float* lin_W   = (const float*)d_in[9];
    const float* lin_b   = (const float*)d_in[10];
    float* out = (float*)d_out;

    // pre-activations (parallel, off the critical chain)
    pre_gemm_kernel<<<dim3(1, G4 / BN), TPB>>>(x, enc_Wih, enc_bih, enc_bhh, 0);
    pre_gemm_kernel<<<dim3((NCOLS * A_DIM) / BM, G4 / BN), TPB>>>(x, dec_Wih, dec_bih, dec_bhh, 1);

    // reset flags + h0 every launch (graph replays)
    init_kernel<<<1, 512>>>();

    // sequential recurrent chain: 16384 steps, persistent 128-CTA grid
    lstm_seq_kernel<<<NCTA, TPB>>>(enc_Whh, dec_Whh, lin_W, lin_b);

    // broadcast to (64, 256, 128)
    bcast_kernel<<<(64u * 256u * 128u) / 256u, 256u>>>(out);
}

// round 7
// speedup vs baseline: 5.9482x; 5.9482x over previous
#include <cuda_runtime.h>
#include <cstdint>
#include <cstddef>

#define A_DIM 64
#define B_DIM 256
#define D_DIM 128
#define H_DIM 512
#define G4    2048
#define NCTA  128
#define TPB   256
#define NCOLS 256

// ---------------- device scratch (static: no allocations allowed) ----------------
__device__ float g_pre_enc[A_DIM * G4];                       // 512 KB
__device__ float g_pre_dec[(size_t)NCOLS * A_DIM * G4];       // 134 MB
// h exchange: per parity, per CTA, one PRIVATE 128B line (words 0..3 hold its 4 h values)
__device__ __align__(128) float g_hp[2][NCTA][32];
// 8 split barrier counters, each on its own 128B line
__device__ __align__(128) unsigned int g_ctr8[8 * 32];
__device__ float g_outs[NCOLS * D_DIM];                       // per-column projections

// ---------------- pre-activation GEMM: pre[m][g] = bih[g]+bhh[g] + dot(Wih[g,:], x_row(m)) ----
#define BM 64
#define BN 64
#define BK 64

__global__ void pre_gemm_kernel(const float* __restrict__ x,
                                const float* __restrict__ Wih,
                                const float* __restrict__ bih,
                                const float* __restrict__ bhh,
                                int dec)
{
    __shared__ float Xs[BM][BK + 1];
    __shared__ float Ws[BN][BK + 1];
    float* __restrict__ outp = dec ? g_pre_dec : g_pre_enc;

    const int m0 = blockIdx.x * BM;
    const int n0 = blockIdx.y * BN;
    const int tid = threadIdx.x;
    const int tx = tid & 15;
    const int ty = tid >> 4;

    float acc[4][4];
#pragma unroll
    for (int r = 0; r < 4; r++)
#pragma unroll
        for (int c = 0; c < 4; c++) acc[r][c] = 0.f;

    const int lr = tid >> 2;         // 0..63 (row this thread loads)
    const int lc = (tid & 3) * 16;   // 0,16,32,48

#pragma unroll
    for (int kit = 0; kit < 2; kit++) {
        const int k0 = kit * BK;
        // X tile (gathered rows)
        {
            const int m = m0 + lr;
            const float* src;
            if (dec) {
                const int i = m >> 6;       // column index
                const int t = m & 63;       // timestep
                src = x + ((size_t)(t * B_DIM + (B_DIM - 1 - i))) * D_DIM + k0 + lc;
            } else {
                src = x + ((size_t)(m * B_DIM + (B_DIM - 1))) * D_DIM + k0 + lc;
            }
#pragma unroll
            for (int q = 0; q < 4; q++) {
                float4 v = *(const float4*)(src + q * 4);
                Xs[lr][lc + q * 4 + 0] = v.x;
                Xs[lr][lc + q * 4 + 1] = v.y;
                Xs[lr][lc + q * 4 + 2] = v.z;
                Xs[lr][lc + q * 4 + 3] = v.w;
            }
        }
        // W tile
        {
            const int g = n0 + lr;
            const float* src = Wih + (size_t)g * D_DIM + k0 + lc;
#pragma unroll
            for (int q = 0; q < 4; q++) {
                float4 v = *(const float4*)(src + q * 4);
                Ws[lr][lc + q * 4 + 0] = v.x;
                Ws[lr][lc + q * 4 + 1] = v.y;
                Ws[lr][lc + q * 4 + 2] = v.z;
                Ws[lr][lc + q * 4 + 3] = v.w;
            }
        }
        __syncthreads();
#pragma unroll 16
        for (int kk = 0; kk < BK; kk++) {
            float a[4], bb[4];
#pragma unroll
            for (int r = 0; r < 4; r++) a[r] = Xs[ty * 4 + r][kk];
#pragma unroll
            for (int c = 0; c < 4; c++) bb[c] = Ws[tx * 4 + c][kk];
#pragma unroll
            for (int r = 0; r < 4; r++)
#pragma unroll
                for (int c = 0; c < 4; c++) acc[r][c] = fmaf(a[r], bb[c], acc[r][c]);
        }
        __syncthreads();
    }
#pragma unroll
    for (int r = 0; r < 4; r++) {
        const int m = m0 + ty * 4 + r;
#pragma unroll
        for (int c = 0; c < 4; c++) {
            const int g = n0 + tx * 4 + c;
            outp[(size_t)m * G4 + g] = acc[r][c] + bih[g] + bhh[g];
        }
    }
}

// ---------------- init (runs every launch: reset h lines + counters) ----------------
__global__ void init_kernel()
{
    const int t = blockIdx.x * blockDim.x + threadIdx.x;
    if (t < 2 * NCTA * 32) ((float*)g_hp)[t] = 0.f;
    if (t < 8 * 32) g_ctr8[t] = 0u;
}

// ---------------- fast activations (MUFU tanh, proven in round 3) ----------------
__device__ __forceinline__ float tanh_fast(float x)
{
    float y;
    asm("tanh.approx.f32 %0, %1;" : "=f"(y) : "f"(x));
    return y;
}
__device__ __forceinline__ float sigm(float x)
{
    return fmaf(tanh_fast(0.5f * x), 0.5f, 0.5f);
}

// ---------------- sequential recurrent kernel ----------------
__global__ void __launch_bounds__(TPB, 1) lstm_seq_kernel(
    const float* __restrict__ enc_Whh,
    const float* __restrict__ dec_Whh,
    const float* __restrict__ lin_W,
    const float* __restrict__ lin_b)
{
    __shared__ float s_h[544];   // padded h: idx(k) = k + 2*(k>>5), conflict-free
    __shared__ float s_g[16];    // gates [type*4 + jloc]
    __shared__ float s_c[4];     // cell state owned by this CTA
    __shared__ float s_red[8];   // projection partials

    const int b    = blockIdx.x;
    const int tid  = threadIdx.x;
    const int w    = tid >> 5;
    const int lane = tid & 31;
    const int lg   = 2 * w + (lane >> 4);   // local gate 0..15  (= type*4 + jloc)
    const int p    = lane & 15;             // k-partition 0..15
    const int jloc = lg & 3;
    const int type = lg >> 2;
    const int grow = type * H_DIM + b * 4 + jloc;  // global gate row
    const int k0   = p * 32;

    // persistent recurrent weights in registers (4 MB total across grid)
    float we[32], wd[32];
#pragma unroll
    for (int m = 0; m < 32; m++) we[m] = enc_Whh[(size_t)grow * H_DIM + k0 + m];
#pragma unroll
    for (int m = 0; m < 32; m++) wd[m] = dec_Whh[(size_t)grow * H_DIM + k0 + m];
    const float lw0 = lin_W[b * H_DIM + 2 * tid];
    const float lw1 = lin_W[b * H_DIM + 2 * tid + 1];
    const float lb  = lin_b[b];

    if (tid < 4) s_c[tid] = 0.f;
    unsigned bar = 0;
    int buf = 0;
    __syncthreads();

    // read the 512-wide h (parity buf) from 128 private peer lines into padded SMEM
    auto stage = [&]() {
        if (tid < NCTA) {
            const float4 hv4 = __ldcg((const float4*)g_hp[buf][tid]);  // h[4t..4t+3]
            const int base = 4 * tid + 2 * (tid >> 3);
            s_h[base + 0] = hv4.x;
            s_h[base + 1] = hv4.y;
            s_h[base + 2] = hv4.z;
            s_h[base + 3] = hv4.w;
        }
        __syncthreads();
    };

    auto step = [&](const float (&wr)[32], const float* __restrict__ pre) {
        const float prev = __ldg(pre + grow);   // in flight before the stage
        stage();
        // dot(Whh[grow, k0:k0+32], h[k0:k0+32]) from padded SMEM (conflict-free float2)
        const float* hp = s_h + 34 * p;
        float s0 = 0.f, s1 = 0.f;
#pragma unroll
        for (int t = 0; t < 16; t++) {
            const float2 hv = *(const float2*)(hp + 2 * t);
            s0 = fmaf(wr[2 * t + 0], hv.x, s0);
            s1 = fmaf(wr[2 * t + 1], hv.y, s1);
        }
        float sum = s0 + s1;
        sum += __shfl_xor_sync(0xffffffffu, sum, 1);
        sum += __shfl_xor_sync(0xffffffffu, sum, 2);
        sum += __shfl_xor_sync(0xffffffffu, sum, 4);
        sum += __shfl_xor_sync(0xffffffffu, sum, 8);
        if (p == 0) s_g[lg] = sum + prev;
        __syncthreads();                         // dots done; s_g ready; s_h reusable
        if (tid < 4) {
            const float gi = s_g[tid];
            const float gf = s_g[4 + tid];
            const float gg = s_g[8 + tid];
            const float go = s_g[12 + tid];
            const float c  = s_c[tid];
            const float cn = fmaf(sigm(gf), c, sigm(gi) * tanh_fast(gg));
            const float hn = sigm(go) * tanh_fast(cn);
            s_c[tid] = cn;
            g_hp[buf ^ 1][b][tid] = hn;          // plain store to our private line
            __threadfence();                     // round-2 proven ordering
        }
        __syncthreads();
        bar++;
        if (tid == 0) {
            // arrive on this CTA's group counter (8 counters, 16 arrivals each)
            asm volatile("red.release.gpu.global.add.u32 [%0], 1;"
                         :: "l"(g_ctr8 + ((b >> 4) << 5)) : "memory");
        }
        if (tid < 8) {
            // each of 8 lanes observes one group counter (128 pollers/line total)
            const unsigned tgt = bar * 16u;
            const unsigned int* cp = g_ctr8 + (tid << 5);
            unsigned v;
            do {
                asm volatile("ld.acquire.gpu.global.u32 %0, [%1];"
                             : "=r"(v) : "l"(cp) : "memory");
            } while (v < tgt);
        }
        __syncthreads();                         // propagate acquire to all warps
        buf ^= 1;
    };

    auto proj = [&](int i) {
        // out_i[d=b] = lin_b[b] + dot(lin_W[b,:], h)  with h = state entering column i
        stage();                                 // g_hp[buf] = newest h, barrier-protected
        const float2 hv = *(const float2*)(s_h + 2 * tid + 2 * (tid >> 4));
        float v = fmaf(lw0, hv.x, lw1 * hv.y);
#pragma unroll
        for (int m = 16; m >= 1; m >>= 1) v += __shfl_xor_sync(0xffffffffu, v, m);
        if (lane == 0) s_red[w] = v;
        __syncthreads();
        if (tid == 0) {
            float acc = lb;
#pragma unroll
            for (int q = 0; q < 8; q++) acc += s_red[q];
            g_outs[(NCOLS - 1 - i) * D_DIM + b] = acc;
        }
    };

    // ---- encoder: 64 steps on batch row 255 only ----
    for (int t = 0; t < A_DIM; t++) step(we, g_pre_enc + (size_t)t * G4);

    // ---- decoder: 256 columns; projection first, then 64 steps (last column's steps dead) ----
    for (int i = 0; i < NCOLS; i++) {
        proj(i);
        if (i < NCOLS - 1) {
            const float* pbase = g_pre_dec + (size_t)i * A_DIM * G4;
            for (int t = 0; t < A_DIM; t++) step(wd, pbase + (size_t)t * G4);
        }
    }
}

// ---------------- broadcast outs (256x128) over leading A dim -> (64,256,128) ----------------
__global__ void bcast_kernel(float* __restrict__ out)
{
    const unsigned idx = blockIdx.x * blockDim.x + threadIdx.x;
    out[idx] = g_outs[idx & (NCOLS * D_DIM - 1)];
}

// ---------------- launch ----------------
extern "C" void kernel_launch(void* const* d_in, const int* in_sizes, int n_in,
                              void* d_out, int out_size)
{
    const float* x       = (const float*)d_in[0];
    const float* enc_Wih = (const float*)d_in[1];
    const float* enc_Whh = (const float*)d_in[2];
    const float* enc_bih = (const float*)d_in[3];
    const float* enc_bhh = (const float*)d_in[4];
    const float* dec_Wih = (const float*)d_in[5];
    const float* dec_Whh = (const float*)d_in[6];
    const float* dec_bih = (const float*)d_in[7];
    const float* dec_bhh = (const float*)d_in[8];
    const float* lin_W   = (const float*)d_in[9];
    const float* lin_b   = (const float*)d_in[10];
    float* out = (float*)d_out;

    // pre-activations (parallel, off the critical chain)
    pre_gemm_kernel<<<dim3(1, G4 / BN), TPB>>>(x, enc_Wih, enc_bih, enc_bhh, 0);
    pre_gemm_kernel<<<dim3((NCOLS * A_DIM) / BM, G4 / BN), TPB>>>(x, dec_Wih, dec_bih, dec_bhh, 1);

    // reset h lines + counters every launch (graph replays)
    init_kernel<<<32, 256>>>();

    // sequential recurrent chain: 16384 steps, persistent 128-CTA grid
    lstm_seq_kernel<<<NCTA, TPB>>>(enc_Whh, dec_Whh, lin_W, lin_b);

    // broadcast to (64, 256, 128)
    bcast_kernel<<<(64u * 256u * 128u) / 256u, 256u>>>(out);
}